// round 13
// baseline (speedup 1.0000x reference)
#include <cuda_runtime.h>

// ---------------------------------------------------------------------------
// B=8, H=W=256, I_DIM=64, K_DIM=64/stream, V_DIM=32/stream, NH=2 (hd_k=32, hd_v=16)
// unfold(256, P=7, NK=4) -> p=7, stride=21, dilation=4, nk=12
// => 144 patches of 49 px; positions {21i+4j} all distinct per dim
// => fold has no overlap; attn writes exactly Sh x Sw, fill writes the rest.
// f32x2 packed fp32 FMA; packed weights+biases via __ldg; stream-0 K weights
// pre-scaled by 1/sqrt(32). R13: attn/fill blocks INTERLEAVED (36:64 per 100)
// so the 134MB DRAM fill overlaps the L1-bound attention instead of tailing.
// ---------------------------------------------------------------------------

#define BDIM 512           // 16 warps
#define N_ATTN 1152        // 8 batches * 144 patches
#define N_FILL 2048        // fill blocks: 16 warps x 4 rows = 64 rows/block

typedef unsigned long long u64;

#define FFMA2(acc, a, b) asm("fma.rn.f32x2 %0, %1, %2, %0;" : "+l"(acc) : "l"(a), "l"(b))
#define DUP2(d, v)       asm("mov.b64 %0, {%1, %1};"        : "=l"(d)   : "f"(v))
#define PACK2(d, lo, hi) asm("mov.b64 %0, {%1, %2};"        : "=l"(d)   : "f"(lo), "f"(hi))
#define UNPACK2(lo, hi, d) asm("mov.b64 {%0, %1}, %2;"      : "=f"(lo), "=f"(hi) : "l"(d))

// 256-bit sampled mask: bit v set iff v = 21*i + 4*j (i<12, j<7).
__device__ __forceinline__ u64 mask_word(int idx) {
    u64 w01 = (idx & 1) ? 0x622233111198888CULL : 0xC444662223311111ULL;
    u64 w23 = (idx & 1) ? 0x88888CC444662223ULL : 0x3111198888CC4446ULL;
    return (idx & 2) ? w23 : w01;
}

// Packed weight-pair buffers (lo = even output channel, hi = odd).
__device__ __align__(16) u64 gWk2[2 * 32 * 64];   // (st*32 + qp)*64 + c ; st0 pre-scaled
__device__ __align__(16) u64 gWv2[2 * 16 * 64];   // (st*16 + qp)*64 + c
__device__ __align__(16) u64 gWp2[32 * 64];       // cp*64 + i
// Packed bias-pair buffers.
__device__ __align__(16) u64 gbk2[64];            // st*32 + qp ; st0 pre-scaled
__device__ __align__(16) u64 gbv2[32];            // st*16 + qp
__device__ __align__(16) u64 gbp2[32];            // cp

__global__ void repack_kernel(const float* __restrict__ Wk, const float* __restrict__ bk,
                              const float* __restrict__ Wv, const float* __restrict__ bv,
                              const float* __restrict__ Wp, const float* __restrict__ bp) {
    const float SCALE = 0.17677669529663687f;     // 1/sqrt(32), folded into stream-0 K
    int t = blockIdx.x * blockDim.x + threadIdx.x;
    int nt = gridDim.x * blockDim.x;
    for (int i = t; i < 4096; i += nt) {            // Wk pairs
        int c = i & 63, qp = (i >> 6) & 31, st = i >> 11;
        float s = st ? 1.f : SCALE;
        u64 d; PACK2(d, Wk[(st * 64 + 2 * qp) * 64 + c] * s,
                        Wk[(st * 64 + 2 * qp + 1) * 64 + c] * s);
        gWk2[i] = d;
    }
    for (int i = t; i < 2048; i += nt) {            // Wv pairs
        int c = i & 63, qp = (i >> 6) & 15, st = i >> 10;
        u64 d; PACK2(d, Wv[(st * 32 + 2 * qp) * 64 + c], Wv[(st * 32 + 2 * qp + 1) * 64 + c]);
        gWv2[i] = d;
    }
    for (int i = t; i < 2048; i += nt) {            // Wp pairs
        int ic = i & 63, cp = i >> 6;
        u64 d; PACK2(d, Wp[(2 * cp) * 64 + ic], Wp[(2 * cp + 1) * 64 + ic]);
        gWp2[i] = d;
    }
    if (t < 64) {                                   // bk pairs (st0 scaled)
        int st = t >> 5;
        float s = st ? 1.f : SCALE;
        u64 d; PACK2(d, bk[2 * t] * s, bk[2 * t + 1] * s);
        gbk2[t] = d;
    }
    if (t < 32) {
        u64 d; PACK2(d, bv[2 * t], bv[2 * t + 1]);
        gbv2[t] = d;
        u64 e; PACK2(e, bp[2 * t], bp[2 * t + 1]);
        gbp2[t] = e;
    }
}

// ---- smem layout (float offsets) ----
constexpr int oX   = 0;
constexpr int oE   = 0;                  // E[(n*49+x)*52 + y]
constexpr int oET  = 5096;               // ET[(n*49+y)*52 + x]
constexpr int oA_SZ = 10192;
constexpr int oK   = oA_SZ;              // K[(st*49+p)*68 + c]
constexpr int oOT  = oA_SZ;              // OT[p*68 + i]
constexpr int oV   = oA_SZ + 6664;       // V[(st*49+p)*36 + d]  (98 rows)
constexpr int SMEMF = oV + 98 * 36;
constexpr int SMEM_BYTES = SMEMF * 4;    // 81536 bytes -> 2 CTAs/SM

__global__ void __launch_bounds__(BDIM, 2)
fused_kernel(const float* __restrict__ x1, const float* __restrict__ x2,
             const float* __restrict__ Wk, const float* __restrict__ bk,
             const float* __restrict__ Wv, const float* __restrict__ bv,
             const float* __restrict__ Wp, const float* __restrict__ bp,
             float* __restrict__ out) {
    const int tid  = threadIdx.x;
    const int lane = tid & 31;
    const int wid  = tid >> 5;

    // ---- Block remap: interleave attn (36) + fill (64) per group of 100 ----
    // 3200 = 32 groups * 100; 32*36 = 1152 attn, 32*64 = 2048 fill.
    const int grp = blockIdx.x / 100;
    const int rr  = blockIdx.x - grp * 100;
    const bool isFill = (rr >= 36);

    // ======================= FILL PATH: warp-per-row ===================
    if (isFill) {
        int fb = grp * 64 + (rr - 36);            // 0..2047
        int g0 = lane, g1 = lane + 32;
        unsigned nib0 = (unsigned)((mask_word(g0 >> 4) >> ((g0 & 15) * 4)) & 0xF);
        unsigned nib1 = (unsigned)((mask_word(g1 >> 4) >> ((g1 & 15) * 4)) & 0xF);
        int rbase = (fb * 16 + wid) * 4;
#pragma unroll
        for (int k = 0; k < 4; k++) {
            int ri = rbase + k;                   // ri = (b*64 + c)*256 + h
            int h = ri & 255;
            int c = (ri >> 8) & 63;
            float v = __ldg(&bp[c]);
            float4 vv = make_float4(v, v, v, v);
            float* rowp = out + (size_t)ri * 256;
            bool hs = (mask_word(h >> 6) >> (h & 63)) & 1;
            if (!hs) {
                reinterpret_cast<float4*>(rowp)[g0] = vv;
                reinterpret_cast<float4*>(rowp)[g1] = vv;
            } else {
                if (nib0 == 0) {
                    reinterpret_cast<float4*>(rowp)[g0] = vv;
                } else {
#pragma unroll
                    for (int q = 0; q < 4; q++)
                        if (!((nib0 >> q) & 1)) rowp[g0 * 4 + q] = v;
                }
                if (nib1 == 0) {
                    reinterpret_cast<float4*>(rowp)[g1] = vv;
                } else {
#pragma unroll
                    for (int q = 0; q < 4; q++)
                        if (!((nib1 >> q) & 1)) rowp[g1 * 4 + q] = v;
                }
            }
        }
        return;
    }

    // ======================= ATTENTION PATH =================================
    extern __shared__ __align__(16) float sm[];
    const bool has1 = (lane < 17);

    const int ab = grp * 36 + rr;                 // 0..1151
    const int b  = ab / 144;
    const int s  = ab % 144;
    const int si = s / 12, sj = s % 12;

    // ---- Phase 1: gather x1/x2; 4 channels per task, STS.128 ----
#pragma unroll 4
    for (int idx = tid; idx < 1568; idx += BDIM) {
        int stcg = idx / 49;
        int p = idx - stcg * 49;
        int st = stcg >> 4;
        int cg = stcg & 15;
        int px = p / 7, py = p % 7;
        int h = si * 21 + px * 4, w = sj * 21 + py * 4;
        const float* xp = (st ? x2 : x1) + ((size_t)(b * 64 + cg * 4) * 256 + h) * 256 + w;
        float4 val;
        val.x = __ldcg(xp);
        val.y = __ldcg(xp + 65536);
        val.z = __ldcg(xp + 131072);
        val.w = __ldcg(xp + 196608);
        *reinterpret_cast<float4*>(&sm[oX + (st * 49 + p) * 68 + cg * 4]) = val;
    }
    __syncthreads();

    // ---- Phase 2: fused K+V 1x1 convs; X loaded once, DUPs shared ----
    {
        const int st  = wid >> 3;
        const int sub = wid & 7;
        const int pp0 = sub * 4;            // 4 K oc-pairs
        const int vp0 = sub * 2;            // 2 V oc-pairs
        const ulonglong2* WK2 = reinterpret_cast<const ulonglong2*>(&gWk2[(st * 32 + pp0) * 64]);
        const ulonglong2* WV2 = reinterpret_cast<const ulonglong2*>(&gWv2[(st * 16 + vp0) * 64]);
        u64 accK[4][2], accV[2][2];
#pragma unroll
        for (int qp = 0; qp < 4; qp++) {
            u64 bb = __ldg(&gbk2[st * 32 + pp0 + qp]);
            accK[qp][0] = bb; accK[qp][1] = bb;
        }
#pragma unroll
        for (int qp = 0; qp < 2; qp++) {
            u64 bb = __ldg(&gbv2[st * 16 + vp0 + qp]);
            accV[qp][0] = bb; accV[qp][1] = bb;
        }
        const float4* xa = reinterpret_cast<const float4*>(&sm[oX + (st * 49 + lane) * 68]);
        const float4* xb = reinterpret_cast<const float4*>(&sm[oX + (st * 49 + lane + 32) * 68]);
#pragma unroll
        for (int i4 = 0; i4 < 16; i4++) {
            float4 a = xa[i4];
            float4 bx = has1 ? xb[i4] : make_float4(0.f, 0.f, 0.f, 0.f);
            u64 da[4], db[4];
            DUP2(da[0], a.x); DUP2(da[1], a.y); DUP2(da[2], a.z); DUP2(da[3], a.w);
            DUP2(db[0], bx.x); DUP2(db[1], bx.y); DUP2(db[2], bx.z); DUP2(db[3], bx.w);
#pragma unroll
            for (int qp = 0; qp < 4; qp++) {
                ulonglong2 w01 = __ldg(&WK2[qp * 32 + i4 * 2]);
                ulonglong2 w23 = __ldg(&WK2[qp * 32 + i4 * 2 + 1]);
                FFMA2(accK[qp][0], w01.x, da[0]); FFMA2(accK[qp][0], w01.y, da[1]);
                FFMA2(accK[qp][0], w23.x, da[2]); FFMA2(accK[qp][0], w23.y, da[3]);
                FFMA2(accK[qp][1], w01.x, db[0]); FFMA2(accK[qp][1], w01.y, db[1]);
                FFMA2(accK[qp][1], w23.x, db[2]); FFMA2(accK[qp][1], w23.y, db[3]);
            }
#pragma unroll
            for (int qp = 0; qp < 2; qp++) {
                ulonglong2 w01 = __ldg(&WV2[qp * 32 + i4 * 2]);
                ulonglong2 w23 = __ldg(&WV2[qp * 32 + i4 * 2 + 1]);
                FFMA2(accV[qp][0], w01.x, da[0]); FFMA2(accV[qp][0], w01.y, da[1]);
                FFMA2(accV[qp][0], w23.x, da[2]); FFMA2(accV[qp][0], w23.y, da[3]);
                FFMA2(accV[qp][1], w01.x, db[0]); FFMA2(accV[qp][1], w01.y, db[1]);
                FFMA2(accV[qp][1], w23.x, db[2]); FFMA2(accV[qp][1], w23.y, db[3]);
            }
        }
        // K stores (float4, conflict-free)
        {
            int oc0 = pp0 * 2;
            int ob0 = oK + (st * 49 + lane) * 68 + oc0;
            int ob1 = oK + (st * 49 + lane + 32) * 68 + oc0;
#pragma unroll
            for (int g = 0; g < 2; g++) {
                float q0, q1, q2, q3;
                UNPACK2(q0, q1, accK[2 * g][0]); UNPACK2(q2, q3, accK[2 * g + 1][0]);
                *reinterpret_cast<float4*>(&sm[ob0 + g * 4]) = make_float4(q0, q1, q2, q3);
                if (has1) {
                    UNPACK2(q0, q1, accK[2 * g][1]); UNPACK2(q2, q3, accK[2 * g + 1][1]);
                    *reinterpret_cast<float4*>(&sm[ob1 + g * 4]) = make_float4(q0, q1, q2, q3);
                }
            }
        }
        // V stores (float4)
        {
            int oc0 = vp0 * 2;
            int ob0 = oV + (st * 49 + lane) * 36 + oc0;
            int ob1 = oV + (st * 49 + lane + 32) * 36 + oc0;
            float q0, q1, q2, q3;
            UNPACK2(q0, q1, accV[0][0]); UNPACK2(q2, q3, accV[1][0]);
            *reinterpret_cast<float4*>(&sm[ob0]) = make_float4(q0, q1, q2, q3);
            if (has1) {
                UNPACK2(q0, q1, accV[0][1]); UNPACK2(q2, q3, accV[1][1]);
                *reinterpret_cast<float4*>(&sm[ob1]) = make_float4(q0, q1, q2, q3);
            }
        }
    }
    __syncthreads();

    // ---- Phase 3: E = exp(k1s . k2) + transposed copy ET (scale prefolded) ----
    {
        int n  = wid >> 3;
        int w8 = wid & 7;
        int x0 = w8 ? (1 + w8 * 6) : 0;          // 0,7,13,19,25,31,37,43
        int R  = w8 ? 6 : 7;
        float acc[7][2];
#pragma unroll
        for (int xx = 0; xx < 7; xx++) { acc[xx][0] = 0.f; acc[xx][1] = 0.f; }
        const float4* k2a = reinterpret_cast<const float4*>(&sm[oK + (49 + lane) * 68 + n * 32]);
        const float4* k2b = reinterpret_cast<const float4*>(&sm[oK + (49 + lane + 32) * 68 + n * 32]);
#pragma unroll
        for (int c4 = 0; c4 < 8; c4++) {
            float4 e0 = k2a[c4];
            float4 e1 = has1 ? k2b[c4] : make_float4(0.f, 0.f, 0.f, 0.f);
#pragma unroll
            for (int xx = 0; xx < 7; xx++) {
                if (xx < R) {
                    float4 k1 = *reinterpret_cast<const float4*>(
                        &sm[oK + (x0 + xx) * 68 + n * 32 + c4 * 4]);     // broadcast
                    acc[xx][0] += k1.x * e0.x + k1.y * e0.y + k1.z * e0.z + k1.w * e0.w;
                    acc[xx][1] += k1.x * e1.x + k1.y * e1.y + k1.z * e1.z + k1.w * e1.w;
                }
            }
        }
#pragma unroll
        for (int xx = 0; xx < 7; xx++) {
            if (xx < R) {
                int x = x0 + xx;
                float v0 = __expf(acc[xx][0]);
                sm[oE + (n * 49 + x) * 52 + lane] = v0;
                sm[oET + (n * 49 + lane) * 52 + x] = v0;
                if (has1) {
                    float v1 = __expf(acc[xx][1]);
                    sm[oE + (n * 49 + x) * 52 + lane + 32] = v1;
                    sm[oET + (n * 49 + lane + 32) * 52 + x] = v1;
                }
            }
        }
    }
    __syncthreads();

    // ---- Phase 5: o1 / o2 -> OT[p][i]; sums folded in; 16 warp-tasks ----
    {
        int which = wid >> 3;
        int n  = (wid >> 2) & 1;
        int dg = wid & 3;
        u64 acc[2][2] = {{0ull, 0ull}, {0ull, 0ull}};
        float ssum0 = 0.f, ssum1 = 0.f;
        int erow0 = (which ? oE : oET) + (n * 49 + lane) * 52;
        int erow1 = (which ? oE : oET) + (n * 49 + lane + 32) * 52;
        int vbase = oV + which * 49 * 36 + n * 16 + dg * 4;
#pragma unroll
        for (int k4 = 0; k4 < 12; k4++) {
            float4 e0 = *reinterpret_cast<const float4*>(&sm[erow0 + k4 * 4]);
            float4 e1 = has1 ? *reinterpret_cast<const float4*>(&sm[erow1 + k4 * 4])
                             : make_float4(0.f, 0.f, 0.f, 0.f);
            ssum0 += e0.x + e0.y + e0.z + e0.w;
            ssum1 += e1.x + e1.y + e1.z + e1.w;
            float ea[4] = {e0.x, e0.y, e0.z, e0.w};
            float eb[4] = {e1.x, e1.y, e1.z, e1.w};
#pragma unroll
            for (int k = 0; k < 4; k++) {
                ulonglong2 v2 = *reinterpret_cast<const ulonglong2*>(&sm[vbase + (k4 * 4 + k) * 36]);
                u64 d0, d1;
                DUP2(d0, ea[k]); DUP2(d1, eb[k]);
                FFMA2(acc[0][0], v2.x, d0); FFMA2(acc[1][0], v2.y, d0);
                FFMA2(acc[0][1], v2.x, d1); FFMA2(acc[1][1], v2.y, d1);
            }
        }
        {   // tail k = 48
            float e0 = sm[erow0 + 48];
            float e1 = has1 ? sm[erow1 + 48] : 0.f;
            ssum0 += e0; ssum1 += e1;
            ulonglong2 v2 = *reinterpret_cast<const ulonglong2*>(&sm[vbase + 48 * 36]);
            u64 d0, d1;
            DUP2(d0, e0); DUP2(d1, e1);
            FFMA2(acc[0][0], v2.x, d0); FFMA2(acc[1][0], v2.y, d0);
            FFMA2(acc[0][1], v2.x, d1); FFMA2(acc[1][1], v2.y, d1);
        }
        float f0 = 1.f / ssum0;
        float f1 = has1 ? (1.f / ssum1) : 0.f;
        int col = which * 32 + n * 16 + dg * 4;
        float a0, a1, a2, a3;
        UNPACK2(a0, a1, acc[0][0]); UNPACK2(a2, a3, acc[1][0]);
        *reinterpret_cast<float4*>(&sm[oOT + lane * 68 + col]) =
            make_float4(a0 * f0, a1 * f0, a2 * f0, a3 * f0);
        if (has1) {
            UNPACK2(a0, a1, acc[0][1]); UNPACK2(a2, a3, acc[1][1]);
            *reinterpret_cast<float4*>(&sm[oOT + (lane + 32) * 68 + col]) =
                make_float4(a0 * f1, a1 * f1, a2 * f1, a3 * f1);
        }
    }
    __syncthreads();

    // ---- Phase 6: Out[c][p] = bp[c] + sum_i OT[p][i]*Wp[c][i]; direct gmem scatter ----
    {
        int c0 = wid * 4;
        int cp0 = wid * 2;
        u64 acc[2][2];
#pragma unroll
        for (int j = 0; j < 2; j++) {
            u64 bb = __ldg(&gbp2[cp0 + j]);
            acc[j][0] = bb; acc[j][1] = bb;
        }
        const ulonglong2* W2 = reinterpret_cast<const ulonglong2*>(&gWp2[cp0 * 64]);
#pragma unroll
        for (int i4 = 0; i4 < 16; i4++) {
            float4 oa = *reinterpret_cast<const float4*>(&sm[oOT + lane * 68 + i4 * 4]);
            float4 ob = has1 ? *reinterpret_cast<const float4*>(&sm[oOT + (lane + 32) * 68 + i4 * 4])
                             : make_float4(0.f, 0.f, 0.f, 0.f);
            u64 da[4], db[4];
            DUP2(da[0], oa.x); DUP2(da[1], oa.y); DUP2(da[2], oa.z); DUP2(da[3], oa.w);
            DUP2(db[0], ob.x); DUP2(db[1], ob.y); DUP2(db[2], ob.z); DUP2(db[3], ob.w);
#pragma unroll
            for (int j = 0; j < 2; j++) {
                ulonglong2 w01 = __ldg(&W2[j * 32 + i4 * 2]);
                ulonglong2 w23 = __ldg(&W2[j * 32 + i4 * 2 + 1]);
                FFMA2(acc[j][0], w01.x, da[0]); FFMA2(acc[j][0], w01.y, da[1]);
                FFMA2(acc[j][0], w23.x, da[2]); FFMA2(acc[j][0], w23.y, da[3]);
                FFMA2(acc[j][1], w01.x, db[0]); FFMA2(acc[j][1], w01.y, db[1]);
                FFMA2(acc[j][1], w23.x, db[2]); FFMA2(acc[j][1], w23.y, db[3]);
            }
        }
        // direct scatter: p0 = lane, p1 = lane + 32
        {
            int p0 = lane;
            int h0 = si * 21 + (p0 / 7) * 4, w0 = sj * 21 + (p0 % 7) * 4;
            float* o0 = out + ((size_t)(b * 64 + c0) * 256 + h0) * 256 + w0;
            float q0, q1, q2, q3;
            UNPACK2(q0, q1, acc[0][0]); UNPACK2(q2, q3, acc[1][0]);
            o0[0 * 65536] = q0; o0[1 * 65536] = q1; o0[2 * 65536] = q2; o0[3 * 65536] = q3;
            if (has1) {
                int p1 = lane + 32;
                int h1 = si * 21 + (p1 / 7) * 4, w1 = sj * 21 + (p1 % 7) * 4;
                float* o1 = out + ((size_t)(b * 64 + c0) * 256 + h1) * 256 + w1;
                UNPACK2(q0, q1, acc[0][1]); UNPACK2(q2, q3, acc[1][1]);
                o1[0 * 65536] = q0; o1[1 * 65536] = q1; o1[2 * 65536] = q2; o1[3 * 65536] = q3;
            }
        }
    }
}

extern "C" void kernel_launch(void* const* d_in, const int* in_sizes, int n_in,
                              void* d_out, int out_size) {
    const float* x1 = (const float*)d_in[0];
    const float* x2 = (const float*)d_in[1];
    const float* Wk = (const float*)d_in[2];
    const float* bk = (const float*)d_in[3];
    const float* Wv = (const float*)d_in[4];
    const float* bv = (const float*)d_in[5];
    const float* Wp = (const float*)d_in[6];
    const float* bp = (const float*)d_in[7];
    float* out = (float*)d_out;

    repack_kernel<<<32, 256>>>(Wk, bk, Wv, bv, Wp, bp);

    cudaFuncSetAttribute(fused_kernel,
                         cudaFuncAttributeMaxDynamicSharedMemorySize, SMEM_BYTES);
    fused_kernel<<<N_ATTN + N_FILL, BDIM, SMEM_BYTES>>>(x1, x2, Wk, bk, Wv, bv, Wp, bp, out);
}

// round 14
// speedup vs baseline: 1.0314x; 1.0314x over previous
#include <cuda_runtime.h>

// ---------------------------------------------------------------------------
// B=8, H=W=256, I_DIM=64, K_DIM=64/stream, V_DIM=32/stream, NH=2 (hd_k=32, hd_v=16)
// unfold(256, P=7, NK=4) -> p=7, stride=21, dilation=4, nk=12
// => 144 patches of 49 px; positions {21i+4j} all distinct per dim
// => fold has no overlap; attn writes exactly Sh x Sw, fill writes the rest.
// f32x2 packed fp32 FMA; packed weights+biases via __ldg; stream-0 K weights
// pre-scaled by 1/sqrt(32). Sequential block order (attn then fill — fill
// overlaps the tail naturally; R13 interleave regressed). Fill stores use
// __stwt (no L2 allocate) to keep L2 for the attention working set.
// ---------------------------------------------------------------------------

#define BDIM 512           // 16 warps
#define N_ATTN 1152        // 8 batches * 144 patches
#define N_FILL 2048        // fill blocks: 16 warps x 4 rows = 64 rows/block

typedef unsigned long long u64;

#define FFMA2(acc, a, b) asm("fma.rn.f32x2 %0, %1, %2, %0;" : "+l"(acc) : "l"(a), "l"(b))
#define DUP2(d, v)       asm("mov.b64 %0, {%1, %1};"        : "=l"(d)   : "f"(v))
#define PACK2(d, lo, hi) asm("mov.b64 %0, {%1, %2};"        : "=l"(d)   : "f"(lo), "f"(hi))
#define UNPACK2(lo, hi, d) asm("mov.b64 {%0, %1}, %2;"      : "=f"(lo), "=f"(hi) : "l"(d))

// 256-bit sampled mask: bit v set iff v = 21*i + 4*j (i<12, j<7).
__device__ __forceinline__ u64 mask_word(int idx) {
    u64 w01 = (idx & 1) ? 0x622233111198888CULL : 0xC444662223311111ULL;
    u64 w23 = (idx & 1) ? 0x88888CC444662223ULL : 0x3111198888CC4446ULL;
    return (idx & 2) ? w23 : w01;
}

// Packed weight-pair buffers (lo = even output channel, hi = odd).
__device__ __align__(16) u64 gWk2[2 * 32 * 64];   // (st*32 + qp)*64 + c ; st0 pre-scaled
__device__ __align__(16) u64 gWv2[2 * 16 * 64];   // (st*16 + qp)*64 + c
__device__ __align__(16) u64 gWp2[32 * 64];       // cp*64 + i
// Packed bias-pair buffers.
__device__ __align__(16) u64 gbk2[64];            // st*32 + qp ; st0 pre-scaled
__device__ __align__(16) u64 gbv2[32];            // st*16 + qp
__device__ __align__(16) u64 gbp2[32];            // cp

__global__ void repack_kernel(const float* __restrict__ Wk, const float* __restrict__ bk,
                              const float* __restrict__ Wv, const float* __restrict__ bv,
                              const float* __restrict__ Wp, const float* __restrict__ bp) {
    const float SCALE = 0.17677669529663687f;     // 1/sqrt(32), folded into stream-0 K
    int t = blockIdx.x * blockDim.x + threadIdx.x;
    int nt = gridDim.x * blockDim.x;
    for (int i = t; i < 4096; i += nt) {            // Wk pairs
        int c = i & 63, qp = (i >> 6) & 31, st = i >> 11;
        float s = st ? 1.f : SCALE;
        u64 d; PACK2(d, Wk[(st * 64 + 2 * qp) * 64 + c] * s,
                        Wk[(st * 64 + 2 * qp + 1) * 64 + c] * s);
        gWk2[i] = d;
    }
    for (int i = t; i < 2048; i += nt) {            // Wv pairs
        int c = i & 63, qp = (i >> 6) & 15, st = i >> 10;
        u64 d; PACK2(d, Wv[(st * 32 + 2 * qp) * 64 + c], Wv[(st * 32 + 2 * qp + 1) * 64 + c]);
        gWv2[i] = d;
    }
    for (int i = t; i < 2048; i += nt) {            // Wp pairs
        int ic = i & 63, cp = i >> 6;
        u64 d; PACK2(d, Wp[(2 * cp) * 64 + ic], Wp[(2 * cp + 1) * 64 + ic]);
        gWp2[i] = d;
    }
    if (t < 64) {                                   // bk pairs (st0 scaled)
        int st = t >> 5;
        float s = st ? 1.f : SCALE;
        u64 d; PACK2(d, bk[2 * t] * s, bk[2 * t + 1] * s);
        gbk2[t] = d;
    }
    if (t < 32) {
        u64 d; PACK2(d, bv[2 * t], bv[2 * t + 1]);
        gbv2[t] = d;
        u64 e; PACK2(e, bp[2 * t], bp[2 * t + 1]);
        gbp2[t] = e;
    }
}

// ---- smem layout (float offsets) ----
constexpr int oX   = 0;
constexpr int oE   = 0;                  // E[(n*49+x)*52 + y]
constexpr int oET  = 5096;               // ET[(n*49+y)*52 + x]
constexpr int oA_SZ = 10192;
constexpr int oK   = oA_SZ;              // K[(st*49+p)*68 + c]
constexpr int oOT  = oA_SZ;              // OT[p*68 + i]
constexpr int oV   = oA_SZ + 6664;       // V[(st*49+p)*36 + d]  (98 rows)
constexpr int SMEMF = oV + 98 * 36;
constexpr int SMEM_BYTES = SMEMF * 4;    // 81536 bytes -> 2 CTAs/SM

__global__ void __launch_bounds__(BDIM, 2)
fused_kernel(const float* __restrict__ x1, const float* __restrict__ x2,
             const float* __restrict__ Wk, const float* __restrict__ bk,
             const float* __restrict__ Wv, const float* __restrict__ bv,
             const float* __restrict__ Wp, const float* __restrict__ bp,
             float* __restrict__ out) {
    const int tid  = threadIdx.x;
    const int lane = tid & 31;
    const int wid  = tid >> 5;

    // ======================= FILL PATH: warp-per-row ===================
    if (blockIdx.x >= N_ATTN) {
        int fb = blockIdx.x - N_ATTN;
        int g0 = lane, g1 = lane + 32;
        unsigned nib0 = (unsigned)((mask_word(g0 >> 4) >> ((g0 & 15) * 4)) & 0xF);
        unsigned nib1 = (unsigned)((mask_word(g1 >> 4) >> ((g1 & 15) * 4)) & 0xF);
        int rbase = (fb * 16 + wid) * 4;
#pragma unroll
        for (int k = 0; k < 4; k++) {
            int ri = rbase + k;                   // ri = (b*64 + c)*256 + h
            int h = ri & 255;
            int c = (ri >> 8) & 63;
            float v = __ldg(&bp[c]);
            float4 vv = make_float4(v, v, v, v);
            float* rowp = out + (size_t)ri * 256;
            bool hs = (mask_word(h >> 6) >> (h & 63)) & 1;
            if (!hs) {
                __stwt(&reinterpret_cast<float4*>(rowp)[g0], vv);
                __stwt(&reinterpret_cast<float4*>(rowp)[g1], vv);
            } else {
                if (nib0 == 0) {
                    __stwt(&reinterpret_cast<float4*>(rowp)[g0], vv);
                } else {
#pragma unroll
                    for (int q = 0; q < 4; q++)
                        if (!((nib0 >> q) & 1)) __stwt(&rowp[g0 * 4 + q], v);
                }
                if (nib1 == 0) {
                    __stwt(&reinterpret_cast<float4*>(rowp)[g1], vv);
                } else {
#pragma unroll
                    for (int q = 0; q < 4; q++)
                        if (!((nib1 >> q) & 1)) __stwt(&rowp[g1 * 4 + q], v);
                }
            }
        }
        return;
    }

    // ======================= ATTENTION PATH =================================
    extern __shared__ __align__(16) float sm[];
    const bool has1 = (lane < 17);

    const int b  = blockIdx.x / 144;
    const int s  = blockIdx.x % 144;
    const int si = s / 12, sj = s % 12;

    // ---- Phase 1: gather x1/x2; 4 channels per task, STS.128 ----
#pragma unroll 4
    for (int idx = tid; idx < 1568; idx += BDIM) {
        int stcg = idx / 49;
        int p = idx - stcg * 49;
        int st = stcg >> 4;
        int cg = stcg & 15;
        int px = p / 7, py = p % 7;
        int h = si * 21 + px * 4, w = sj * 21 + py * 4;
        const float* xp = (st ? x2 : x1) + ((size_t)(b * 64 + cg * 4) * 256 + h) * 256 + w;
        float4 val;
        val.x = __ldcg(xp);
        val.y = __ldcg(xp + 65536);
        val.z = __ldcg(xp + 131072);
        val.w = __ldcg(xp + 196608);
        *reinterpret_cast<float4*>(&sm[oX + (st * 49 + p) * 68 + cg * 4]) = val;
    }
    __syncthreads();

    // ---- Phase 2: fused K+V 1x1 convs; X loaded once, DUPs shared ----
    {
        const int st  = wid >> 3;
        const int sub = wid & 7;
        const int pp0 = sub * 4;            // 4 K oc-pairs
        const int vp0 = sub * 2;            // 2 V oc-pairs
        const ulonglong2* WK2 = reinterpret_cast<const ulonglong2*>(&gWk2[(st * 32 + pp0) * 64]);
        const ulonglong2* WV2 = reinterpret_cast<const ulonglong2*>(&gWv2[(st * 16 + vp0) * 64]);
        u64 accK[4][2], accV[2][2];
#pragma unroll
        for (int qp = 0; qp < 4; qp++) {
            u64 bb = __ldg(&gbk2[st * 32 + pp0 + qp]);
            accK[qp][0] = bb; accK[qp][1] = bb;
        }
#pragma unroll
        for (int qp = 0; qp < 2; qp++) {
            u64 bb = __ldg(&gbv2[st * 16 + vp0 + qp]);
            accV[qp][0] = bb; accV[qp][1] = bb;
        }
        const float4* xa = reinterpret_cast<const float4*>(&sm[oX + (st * 49 + lane) * 68]);
        const float4* xb = reinterpret_cast<const float4*>(&sm[oX + (st * 49 + lane + 32) * 68]);
#pragma unroll
        for (int i4 = 0; i4 < 16; i4++) {
            float4 a = xa[i4];
            float4 bx = has1 ? xb[i4] : make_float4(0.f, 0.f, 0.f, 0.f);
            u64 da[4], db[4];
            DUP2(da[0], a.x); DUP2(da[1], a.y); DUP2(da[2], a.z); DUP2(da[3], a.w);
            DUP2(db[0], bx.x); DUP2(db[1], bx.y); DUP2(db[2], bx.z); DUP2(db[3], bx.w);
#pragma unroll
            for (int qp = 0; qp < 4; qp++) {
                ulonglong2 w01 = __ldg(&WK2[qp * 32 + i4 * 2]);
                ulonglong2 w23 = __ldg(&WK2[qp * 32 + i4 * 2 + 1]);
                FFMA2(accK[qp][0], w01.x, da[0]); FFMA2(accK[qp][0], w01.y, da[1]);
                FFMA2(accK[qp][0], w23.x, da[2]); FFMA2(accK[qp][0], w23.y, da[3]);
                FFMA2(accK[qp][1], w01.x, db[0]); FFMA2(accK[qp][1], w01.y, db[1]);
                FFMA2(accK[qp][1], w23.x, db[2]); FFMA2(accK[qp][1], w23.y, db[3]);
            }
#pragma unroll
            for (int qp = 0; qp < 2; qp++) {
                ulonglong2 w01 = __ldg(&WV2[qp * 32 + i4 * 2]);
                ulonglong2 w23 = __ldg(&WV2[qp * 32 + i4 * 2 + 1]);
                FFMA2(accV[qp][0], w01.x, da[0]); FFMA2(accV[qp][0], w01.y, da[1]);
                FFMA2(accV[qp][0], w23.x, da[2]); FFMA2(accV[qp][0], w23.y, da[3]);
                FFMA2(accV[qp][1], w01.x, db[0]); FFMA2(accV[qp][1], w01.y, db[1]);
                FFMA2(accV[qp][1], w23.x, db[2]); FFMA2(accV[qp][1], w23.y, db[3]);
            }
        }
        // K stores (float4, conflict-free)
        {
            int oc0 = pp0 * 2;
            int ob0 = oK + (st * 49 + lane) * 68 + oc0;
            int ob1 = oK + (st * 49 + lane + 32) * 68 + oc0;
#pragma unroll
            for (int g = 0; g < 2; g++) {
                float q0, q1, q2, q3;
                UNPACK2(q0, q1, accK[2 * g][0]); UNPACK2(q2, q3, accK[2 * g + 1][0]);
                *reinterpret_cast<float4*>(&sm[ob0 + g * 4]) = make_float4(q0, q1, q2, q3);
                if (has1) {
                    UNPACK2(q0, q1, accK[2 * g][1]); UNPACK2(q2, q3, accK[2 * g + 1][1]);
                    *reinterpret_cast<float4*>(&sm[ob1 + g * 4]) = make_float4(q0, q1, q2, q3);
                }
            }
        }
        // V stores (float4)
        {
            int oc0 = vp0 * 2;
            int ob0 = oV + (st * 49 + lane) * 36 + oc0;
            int ob1 = oV + (st * 49 + lane + 32) * 36 + oc0;
            float q0, q1, q2, q3;
            UNPACK2(q0, q1, accV[0][0]); UNPACK2(q2, q3, accV[1][0]);
            *reinterpret_cast<float4*>(&sm[ob0]) = make_float4(q0, q1, q2, q3);
            if (has1) {
                UNPACK2(q0, q1, accV[0][1]); UNPACK2(q2, q3, accV[1][1]);
                *reinterpret_cast<float4*>(&sm[ob1]) = make_float4(q0, q1, q2, q3);
            }
        }
    }
    __syncthreads();

    // ---- Phase 3: E = exp(k1s . k2) + transposed copy ET (scale prefolded) ----
    {
        int n  = wid >> 3;
        int w8 = wid & 7;
        int x0 = w8 ? (1 + w8 * 6) : 0;          // 0,7,13,19,25,31,37,43
        int R  = w8 ? 6 : 7;
        float acc[7][2];
#pragma unroll
        for (int xx = 0; xx < 7; xx++) { acc[xx][0] = 0.f; acc[xx][1] = 0.f; }
        const float4* k2a = reinterpret_cast<const float4*>(&sm[oK + (49 + lane) * 68 + n * 32]);
        const float4* k2b = reinterpret_cast<const float4*>(&sm[oK + (49 + lane + 32) * 68 + n * 32]);
#pragma unroll
        for (int c4 = 0; c4 < 8; c4++) {
            float4 e0 = k2a[c4];
            float4 e1 = has1 ? k2b[c4] : make_float4(0.f, 0.f, 0.f, 0.f);
#pragma unroll
            for (int xx = 0; xx < 7; xx++) {
                if (xx < R) {
                    float4 k1 = *reinterpret_cast<const float4*>(
                        &sm[oK + (x0 + xx) * 68 + n * 32 + c4 * 4]);     // broadcast
                    acc[xx][0] += k1.x * e0.x + k1.y * e0.y + k1.z * e0.z + k1.w * e0.w;
                    acc[xx][1] += k1.x * e1.x + k1.y * e1.y + k1.z * e1.z + k1.w * e1.w;
                }
            }
        }
#pragma unroll
        for (int xx = 0; xx < 7; xx++) {
            if (xx < R) {
                int x = x0 + xx;
                float v0 = __expf(acc[xx][0]);
                sm[oE + (n * 49 + x) * 52 + lane] = v0;
                sm[oET + (n * 49 + lane) * 52 + x] = v0;
                if (has1) {
                    float v1 = __expf(acc[xx][1]);
                    sm[oE + (n * 49 + x) * 52 + lane + 32] = v1;
                    sm[oET + (n * 49 + lane + 32) * 52 + x] = v1;
                }
            }
        }
    }
    __syncthreads();

    // ---- Phase 5: o1 / o2 -> OT[p][i]; sums folded in; 16 warp-tasks ----
    {
        int which = wid >> 3;
        int n  = (wid >> 2) & 1;
        int dg = wid & 3;
        u64 acc[2][2] = {{0ull, 0ull}, {0ull, 0ull}};
        float ssum0 = 0.f, ssum1 = 0.f;
        int erow0 = (which ? oE : oET) + (n * 49 + lane) * 52;
        int erow1 = (which ? oE : oET) + (n * 49 + lane + 32) * 52;
        int vbase = oV + which * 49 * 36 + n * 16 + dg * 4;
#pragma unroll
        for (int k4 = 0; k4 < 12; k4++) {
            float4 e0 = *reinterpret_cast<const float4*>(&sm[erow0 + k4 * 4]);
            float4 e1 = has1 ? *reinterpret_cast<const float4*>(&sm[erow1 + k4 * 4])
                             : make_float4(0.f, 0.f, 0.f, 0.f);
            ssum0 += e0.x + e0.y + e0.z + e0.w;
            ssum1 += e1.x + e1.y + e1.z + e1.w;
            float ea[4] = {e0.x, e0.y, e0.z, e0.w};
            float eb[4] = {e1.x, e1.y, e1.z, e1.w};
#pragma unroll
            for (int k = 0; k < 4; k++) {
                ulonglong2 v2 = *reinterpret_cast<const ulonglong2*>(&sm[vbase + (k4 * 4 + k) * 36]);
                u64 d0, d1;
                DUP2(d0, ea[k]); DUP2(d1, eb[k]);
                FFMA2(acc[0][0], v2.x, d0); FFMA2(acc[1][0], v2.y, d0);
                FFMA2(acc[0][1], v2.x, d1); FFMA2(acc[1][1], v2.y, d1);
            }
        }
        {   // tail k = 48
            float e0 = sm[erow0 + 48];
            float e1 = has1 ? sm[erow1 + 48] : 0.f;
            ssum0 += e0; ssum1 += e1;
            ulonglong2 v2 = *reinterpret_cast<const ulonglong2*>(&sm[vbase + 48 * 36]);
            u64 d0, d1;
            DUP2(d0, e0); DUP2(d1, e1);
            FFMA2(acc[0][0], v2.x, d0); FFMA2(acc[1][0], v2.y, d0);
            FFMA2(acc[0][1], v2.x, d1); FFMA2(acc[1][1], v2.y, d1);
        }
        float f0 = 1.f / ssum0;
        float f1 = has1 ? (1.f / ssum1) : 0.f;
        int col = which * 32 + n * 16 + dg * 4;
        float a0, a1, a2, a3;
        UNPACK2(a0, a1, acc[0][0]); UNPACK2(a2, a3, acc[1][0]);
        *reinterpret_cast<float4*>(&sm[oOT + lane * 68 + col]) =
            make_float4(a0 * f0, a1 * f0, a2 * f0, a3 * f0);
        if (has1) {
            UNPACK2(a0, a1, acc[0][1]); UNPACK2(a2, a3, acc[1][1]);
            *reinterpret_cast<float4*>(&sm[oOT + (lane + 32) * 68 + col]) =
                make_float4(a0 * f1, a1 * f1, a2 * f1, a3 * f1);
        }
    }
    __syncthreads();

    // ---- Phase 6: Out[c][p] = bp[c] + sum_i OT[p][i]*Wp[c][i]; direct gmem scatter ----
    {
        int c0 = wid * 4;
        int cp0 = wid * 2;
        u64 acc[2][2];
#pragma unroll
        for (int j = 0; j < 2; j++) {
            u64 bb = __ldg(&gbp2[cp0 + j]);
            acc[j][0] = bb; acc[j][1] = bb;
        }
        const ulonglong2* W2 = reinterpret_cast<const ulonglong2*>(&gWp2[cp0 * 64]);
#pragma unroll
        for (int i4 = 0; i4 < 16; i4++) {
            float4 oa = *reinterpret_cast<const float4*>(&sm[oOT + lane * 68 + i4 * 4]);
            float4 ob = has1 ? *reinterpret_cast<const float4*>(&sm[oOT + (lane + 32) * 68 + i4 * 4])
                             : make_float4(0.f, 0.f, 0.f, 0.f);
            u64 da[4], db[4];
            DUP2(da[0], oa.x); DUP2(da[1], oa.y); DUP2(da[2], oa.z); DUP2(da[3], oa.w);
            DUP2(db[0], ob.x); DUP2(db[1], ob.y); DUP2(db[2], ob.z); DUP2(db[3], ob.w);
#pragma unroll
            for (int j = 0; j < 2; j++) {
                ulonglong2 w01 = __ldg(&W2[j * 32 + i4 * 2]);
                ulonglong2 w23 = __ldg(&W2[j * 32 + i4 * 2 + 1]);
                FFMA2(acc[j][0], w01.x, da[0]); FFMA2(acc[j][0], w01.y, da[1]);
                FFMA2(acc[j][0], w23.x, da[2]); FFMA2(acc[j][0], w23.y, da[3]);
                FFMA2(acc[j][1], w01.x, db[0]); FFMA2(acc[j][1], w01.y, db[1]);
                FFMA2(acc[j][1], w23.x, db[2]); FFMA2(acc[j][1], w23.y, db[3]);
            }
        }
        // direct scatter: p0 = lane, p1 = lane + 32
        {
            int p0 = lane;
            int h0 = si * 21 + (p0 / 7) * 4, w0 = sj * 21 + (p0 % 7) * 4;
            float* o0 = out + ((size_t)(b * 64 + c0) * 256 + h0) * 256 + w0;
            float q0, q1, q2, q3;
            UNPACK2(q0, q1, acc[0][0]); UNPACK2(q2, q3, acc[1][0]);
            o0[0 * 65536] = q0; o0[1 * 65536] = q1; o0[2 * 65536] = q2; o0[3 * 65536] = q3;
            if (has1) {
                int p1 = lane + 32;
                int h1 = si * 21 + (p1 / 7) * 4, w1 = sj * 21 + (p1 % 7) * 4;
                float* o1 = out + ((size_t)(b * 64 + c0) * 256 + h1) * 256 + w1;
                UNPACK2(q0, q1, acc[0][1]); UNPACK2(q2, q3, acc[1][1]);
                o1[0 * 65536] = q0; o1[1 * 65536] = q1; o1[2 * 65536] = q2; o1[3 * 65536] = q3;
            }
        }
    }
}

extern "C" void kernel_launch(void* const* d_in, const int* in_sizes, int n_in,
                              void* d_out, int out_size) {
    const float* x1 = (const float*)d_in[0];
    const float* x2 = (const float*)d_in[1];
    const float* Wk = (const float*)d_in[2];
    const float* bk = (const float*)d_in[3];
    const float* Wv = (const float*)d_in[4];
    const float* bv = (const float*)d_in[5];
    const float* Wp = (const float*)d_in[6];
    const float* bp = (const float*)d_in[7];
    float* out = (float*)d_out;

    repack_kernel<<<32, 256>>>(Wk, bk, Wv, bv, Wp, bp);

    cudaFuncSetAttribute(fused_kernel,
                         cudaFuncAttributeMaxDynamicSharedMemorySize, SMEM_BYTES);
    fused_kernel<<<N_ATTN + N_FILL, BDIM, SMEM_BYTES>>>(x1, x2, Wk, bk, Wv, bv, Wp, bp, out);
}